// round 2
// baseline (speedup 1.0000x reference)
#include <cuda_runtime.h>
#include <math.h>

// Problem constants
#define RR   1024        // num rois
#define GG   16          // groups
#define DD   1024        // feature dim
#define DGB  64          // per-group dim
#define EE   64          // pos-emb dim
#define KFC1 12544       // 256*7*7

// ---------------- scratch (static device globals; no allocation) ----------------
__device__ float g_h  [RR*DD];
__device__ float g_h2 [RR*DD];
__device__ float g_q  [RR*DD];
__device__ float g_k  [RR*DD];
__device__ float g_v  [RR*DD];
__device__ float g_att[RR*DD];
__device__ float g_S  [(long)GG*RR*RR];   // [g][i][j]
__device__ float g_B1 [(long)RR*GG*RR];   // log-bias block1: [r][g][n]
__device__ float g_B2 [(long)RR*GG*RR];   // log-bias block2

// ---------------- position bias kernel ----------------
// out{1,2}[r][g][n] = log(max( pe[r,n,:]·Wp{1,2}[g,:] + bp{1,2}[g], 1e-6 ))
__global__ __launch_bounds__(128)
void posbias_kernel(const float* __restrict__ pe,
                    const float* __restrict__ Wp1, const float* __restrict__ bp1,
                    const float* __restrict__ Wp2, const float* __restrict__ bp2,
                    float* __restrict__ out1, float* __restrict__ out2)
{
    const int r = blockIdx.x;
    const int n = blockIdx.y * 128 + threadIdx.x;

    __shared__ float w1[GG][EE], w2[GG][EE];
    __shared__ float b1s[GG], b2s[GG];
    for (int idx = threadIdx.x; idx < GG*EE; idx += 128) {
        w1[idx >> 6][idx & 63] = Wp1[idx];
        w2[idx >> 6][idx & 63] = Wp2[idx];
    }
    if (threadIdx.x < GG) { b1s[threadIdx.x] = bp1[threadIdx.x]; b2s[threadIdx.x] = bp2[threadIdx.x]; }
    __syncthreads();

    float4 pr[EE/4];
    const float4* src = (const float4*)(pe + (((long)r * RR) + n) * EE);
#pragma unroll
    for (int i = 0; i < EE/4; i++) pr[i] = src[i];

#pragma unroll 1
    for (int g = 0; g < GG; ++g) {
        const float4* a = (const float4*)w1[g];
        const float4* b = (const float4*)w2[g];
        float s1 = 0.f, s2 = 0.f;
#pragma unroll
        for (int i = 0; i < EE/4; i++) {
            float4 p = pr[i], xx = a[i], yy = b[i];
            s1 += p.x*xx.x + p.y*xx.y + p.z*xx.z + p.w*xx.w;
            s2 += p.x*yy.x + p.y*yy.y + p.z*yy.z + p.w*yy.w;
        }
        long o = ((long)r * GG + g) * RR + n;
        out1[o] = logf(fmaxf(s1 + b1s[g], 1e-6f));
        out2[o] = logf(fmaxf(s2 + b2s[g], 1e-6f));
    }
}

// ---------------- generic tiled SGEMM ----------------
// C[M,N] = alpha * A @ op(B) + bias, optional relu.
//   BT=true : B is [N,K] row-major (i.e. C = A @ B^T)  -- weight layout
//   BT=false: B is [K,N] row-major (i.e. C = A @ B)
//   CONCAT  : virtual A = [h | a | h+a] over K=3072 (A=h, A2=a)
// z-batching via aZ/bZ/cZ/biasZ element offsets per blockIdx.z.
template<int BM,int BN,int BK,int TM,int TN,bool BT,bool CONCAT>
__global__ void __launch_bounds__((BM/TM)*(BN/TN))
gemm_k(const float* __restrict__ A, const float* __restrict__ A2, int lda,
       const float* __restrict__ B, int ldb,
       float* __restrict__ C, int ldc,
       int M, int N, int K, float alpha,
       const float* __restrict__ bias, int doRelu,
       long aZ, long bZ, long cZ, long biasZ)
{
    constexpr int THREADS = (BM/TM)*(BN/TN);
    constexpr int LA = (BM*BK)/(4*THREADS);
    constexpr int LB = (BN*BK)/(4*THREADS);
    static_assert(LA >= 1 && LB >= 1, "tile/thread mismatch");

    const int tid = threadIdx.x;
    const int tx  = tid % (BN/TN);
    const int ty  = tid / (BN/TN);
    const int m0  = blockIdx.y * BM;
    const int n0  = blockIdx.x * BN;
    const long z  = blockIdx.z;

    A += z * aZ;
    if (CONCAT) A2 += z * aZ;
    B += z * bZ;
    C += z * cZ;
    const float* biasP = bias ? (bias + z * biasZ) : nullptr;

    __shared__ float As[BK][BM];
    __shared__ float Bs[BK][BN];

    float acc[TM][TN];
#pragma unroll
    for (int i = 0; i < TM; i++)
#pragma unroll
        for (int j = 0; j < TN; j++) acc[i][j] = 0.f;

    float4 pa[LA], pb[LB];

    auto loadA4 = [&](int row, int col) -> float4 {
        if (!CONCAT) {
            return *(const float4*)(A + (long)row * lda + col);
        } else {
            if (col < DD) {
                return *(const float4*)(A + (long)row * DD + col);
            } else if (col < 2*DD) {
                return *(const float4*)(A2 + (long)row * DD + (col - DD));
            } else {
                float4 h4 = *(const float4*)(A  + (long)row * DD + (col - 2*DD));
                float4 a4 = *(const float4*)(A2 + (long)row * DD + (col - 2*DD));
                return make_float4(h4.x+a4.x, h4.y+a4.y, h4.z+a4.z, h4.w+a4.w);
            }
        }
    };

    auto gload = [&](int t) {
        const int k0 = t * BK;
#pragma unroll
        for (int i = 0; i < LA; i++) {
            int idx = tid + i * THREADS;
            int am  = idx / (BK/4);
            int ak  = (idx % (BK/4)) * 4;
            pa[i] = loadA4(m0 + am, k0 + ak);
        }
#pragma unroll
        for (int i = 0; i < LB; i++) {
            int idx = tid + i * THREADS;
            if (BT) {
                int bn = idx / (BK/4);
                int bk = (idx % (BK/4)) * 4;
                pb[i] = *(const float4*)(B + (long)(n0 + bn) * ldb + k0 + bk);
            } else {
                int bk = idx / (BN/4);
                int bn = (idx % (BN/4)) * 4;
                pb[i] = *(const float4*)(B + (long)(k0 + bk) * ldb + n0 + bn);
            }
        }
    };

    auto smstore = [&]() {
#pragma unroll
        for (int i = 0; i < LA; i++) {
            int idx = tid + i * THREADS;
            int am  = idx / (BK/4);
            int ak  = (idx % (BK/4)) * 4;
            As[ak+0][am] = pa[i].x; As[ak+1][am] = pa[i].y;
            As[ak+2][am] = pa[i].z; As[ak+3][am] = pa[i].w;
        }
#pragma unroll
        for (int i = 0; i < LB; i++) {
            int idx = tid + i * THREADS;
            if (BT) {
                int bn = idx / (BK/4);
                int bk = (idx % (BK/4)) * 4;
                Bs[bk+0][bn] = pb[i].x; Bs[bk+1][bn] = pb[i].y;
                Bs[bk+2][bn] = pb[i].z; Bs[bk+3][bn] = pb[i].w;
            } else {
                int bk = idx / (BN/4);
                int bn = (idx % (BN/4)) * 4;
                *(float4*)&Bs[bk][bn] = pb[i];
            }
        }
    };

    const int ntiles = K / BK;
    gload(0);
    smstore();
    __syncthreads();

    for (int t = 0; t < ntiles; t++) {
        if (t + 1 < ntiles) gload(t + 1);   // register prefetch of next tile
#pragma unroll
        for (int kk = 0; kk < BK; kk++) {
            float af[TM], bf[TN];
#pragma unroll
            for (int i = 0; i < TM/4; i++)
                *(float4*)&af[i*4] = *(const float4*)&As[kk][ty*TM + i*4];
#pragma unroll
            for (int j = 0; j < TN/4; j++)
                *(float4*)&bf[j*4] = *(const float4*)&Bs[kk][tx*TN + j*4];
#pragma unroll
            for (int i = 0; i < TM; i++)
#pragma unroll
                for (int j = 0; j < TN; j++)
                    acc[i][j] = fmaf(af[i], bf[j], acc[i][j]);
        }
        if (t + 1 < ntiles) {
            __syncthreads();
            smstore();
            __syncthreads();
        }
    }

    float bb[TN];
#pragma unroll
    for (int j = 0; j < TN; j++) bb[j] = biasP ? biasP[n0 + tx*TN + j] : 0.f;
#pragma unroll
    for (int i = 0; i < TM; i++) {
        int m = m0 + ty*TM + i;
        float4 vo;
        float* vv = &vo.x;
#pragma unroll
        for (int j = 0; j < TN; j++) {
            float r = acc[i][j] * alpha + bb[j];
            if (doRelu) r = fmaxf(r, 0.f);
            vv[j] = r;
        }
        *(float4*)(C + (long)m * ldc + n0 + tx*TN) = vo;
    }
}

// ---------------- fused bias-add + softmax over j ----------------
// S[g][i][:] = softmax( S[g][i][:] + biasLog[i][g][:] )
__global__ __launch_bounds__(256)
void softmax_kernel(float* __restrict__ S, const float* __restrict__ bias)
{
    const int i = blockIdx.x;
    const int g = blockIdx.y;
    float* row = S + ((long)g * RR + i) * RR;
    const float* brow = bias + ((long)i * GG + g) * RR;
    const int tid = threadIdx.x;

    float w[4];
    float mx = -1e30f;
#pragma unroll
    for (int j = 0; j < 4; j++) {
        int c = tid + j * 256;
        w[j] = row[c] + brow[c];
        mx = fmaxf(mx, w[j]);
    }
    __shared__ float red[8];
#pragma unroll
    for (int o = 16; o > 0; o >>= 1) mx = fmaxf(mx, __shfl_xor_sync(0xffffffffu, mx, o));
    if ((tid & 31) == 0) red[tid >> 5] = mx;
    __syncthreads();
    float m2 = red[0];
#pragma unroll
    for (int kk = 1; kk < 8; kk++) m2 = fmaxf(m2, red[kk]);

    float sum = 0.f;
#pragma unroll
    for (int j = 0; j < 4; j++) { w[j] = __expf(w[j] - m2); sum += w[j]; }
#pragma unroll
    for (int o = 16; o > 0; o >>= 1) sum += __shfl_xor_sync(0xffffffffu, sum, o);
    __syncthreads();
    if ((tid & 31) == 0) red[tid >> 5] = sum;
    __syncthreads();
    float s2 = 0.f;
#pragma unroll
    for (int kk = 0; kk < 8; kk++) s2 += red[kk];
    float inv = 1.f / s2;
#pragma unroll
    for (int j = 0; j < 4; j++) row[tid + j * 256] = w[j] * inv;
}

// ---------------- host-side orchestration ----------------
static void relation_block(const float* h, float* q, float* k, float* v,
                           float* S, float* att,
                           const float* Wq, const float* bq,
                           const float* Wk, const float* bk,
                           const float* Wo, const float* bo,
                           const float* biasLog)
{
    // Q = h Wq^T + bq ; K = h Wk^T + bk ; V = h Wo^T   (grouped output proj folded in)
    gemm_k<64,64,16,4,4,true,false><<<dim3(16,16,1),256>>>(
        h,nullptr,DD, Wq,DD, q,DD, RR,DD,DD, 1.f, bq,0, 0,0,0,0);
    gemm_k<64,64,16,4,4,true,false><<<dim3(16,16,1),256>>>(
        h,nullptr,DD, Wk,DD, k,DD, RR,DD,DD, 1.f, bk,0, 0,0,0,0);
    gemm_k<64,64,16,4,4,true,false><<<dim3(16,16,1),256>>>(
        h,nullptr,DD, Wo,DD, v,DD, RR,DD,DD, 1.f, nullptr,0, 0,0,0,0);
    // S[g] = 0.125 * Q_g K_g^T   (batched over 16 groups via grid.z)
    gemm_k<128,64,16,8,4,true,false><<<dim3(16,8,GG),256>>>(
        q,nullptr,DD, k,DD, S,RR, RR,RR,DGB, 0.125f, nullptr,0,
        DGB, DGB, (long)RR*RR, 0);
    // softmax with log-bias
    softmax_kernel<<<dim3(RR,GG),256>>>(S, biasLog);
    // att[:, g*64:(g+1)*64] = A_g @ V_g + bo_g
    gemm_k<64,64,16,4,4,false,false><<<dim3(1,16,GG),256>>>(
        S,nullptr,RR, v,DD, att,DD, RR,DGB,RR, 1.f, bo,0,
        (long)RR*RR, DGB, DGB, DGB);
}

extern "C" void kernel_launch(void* const* d_in, const int* in_sizes, int n_in,
                              void* d_out, int out_size)
{
    const float* x    = (const float*)d_in[0];
    const float* pe   = (const float*)d_in[1];
    const float* Wfc1 = (const float*)d_in[2];
    const float* bfc1 = (const float*)d_in[3];
    const float* Wfc2 = (const float*)d_in[4];
    const float* bfc2 = (const float*)d_in[5];
    const float* Wp1  = (const float*)d_in[6];
    const float* bp1  = (const float*)d_in[7];
    const float* Wq1  = (const float*)d_in[8];
    const float* bq1  = (const float*)d_in[9];
    const float* Wk1  = (const float*)d_in[10];
    const float* bk1  = (const float*)d_in[11];
    const float* Wo1  = (const float*)d_in[12];
    const float* bo1  = (const float*)d_in[13];
    const float* Wa1  = (const float*)d_in[14];
    const float* ba1  = (const float*)d_in[15];
    const float* Wp2  = (const float*)d_in[16];
    const float* bp2  = (const float*)d_in[17];
    const float* Wq2  = (const float*)d_in[18];
    const float* bq2  = (const float*)d_in[19];
    const float* Wk2  = (const float*)d_in[20];
    const float* bk2  = (const float*)d_in[21];
    const float* Wo2  = (const float*)d_in[22];
    const float* bo2  = (const float*)d_in[23];
    const float* Wa2  = (const float*)d_in[24];
    const float* ba2  = (const float*)d_in[25];
    float* out = (float*)d_out;

    float *h, *h2, *q, *k, *v, *att, *S, *B1, *B2;
    cudaGetSymbolAddress((void**)&h,   g_h);
    cudaGetSymbolAddress((void**)&h2,  g_h2);
    cudaGetSymbolAddress((void**)&q,   g_q);
    cudaGetSymbolAddress((void**)&k,   g_k);
    cudaGetSymbolAddress((void**)&v,   g_v);
    cudaGetSymbolAddress((void**)&att, g_att);
    cudaGetSymbolAddress((void**)&S,   g_S);
    cudaGetSymbolAddress((void**)&B1,  g_B1);
    cudaGetSymbolAddress((void**)&B2,  g_B2);

    // Position log-bias for BOTH blocks: single pass over the 268 MB pe tensor
    posbias_kernel<<<dim3(RR, RR/128), 128>>>(pe, Wp1, bp1, Wp2, bp2, B1, B2);

    // fc1: h = x_flat @ Wfc1^T + bfc1      (1024 x 12544 x 1024)
    gemm_k<128,64,16,8,4,true,false><<<dim3(16,8,1),256>>>(
        x,nullptr,KFC1, Wfc1,KFC1, h,DD, RR,DD,KFC1, 1.f, bfc1,0, 0,0,0,0);

    // relation block 1
    relation_block(h, q, k, v, S, att, Wq1, bq1, Wk1, bk1, Wo1, bo1, B1);

    // h2 = relu([h | a1 | h+a1] @ Wa1^T + ba1)   (virtual concat, K=3072)
    gemm_k<128,64,16,8,4,true,true><<<dim3(16,8,1),256>>>(
        h,att,0, Wa1,3*DD, h2,DD, RR,DD,3*DD, 1.f, ba1,1, 0,0,0,0);

    // fc2: h = h2 @ Wfc2^T + bfc2
    gemm_k<64,64,16,4,4,true,false><<<dim3(16,16,1),256>>>(
        h2,nullptr,DD, Wfc2,DD, h,DD, RR,DD,DD, 1.f, bfc2,0, 0,0,0,0);

    // relation block 2
    relation_block(h, q, k, v, S, att, Wq2, bq2, Wk2, bk2, Wo2, bo2, B2);

    // out = relu([h | a2 | h+a2] @ Wa2^T + ba2)
    gemm_k<128,64,16,8,4,true,true><<<dim3(16,8,1),256>>>(
        h,att,0, Wa2,3*DD, out,DD, RR,DD,3*DD, 1.f, ba2,1, 0,0,0,0);
}

// round 7
// speedup vs baseline: 2.6754x; 2.6754x over previous
#include <cuda_runtime.h>
#include <cuda_bf16.h>
#include <math.h>
#include <stdint.h>

#define RR   1024
#define GG   16
#define DD   1024
#define DGB  64
#define EE   64
#define KFC1 12544

#define SWZ(o) ((o) ^ (((o) >> 3) & 0x70))

__device__ __forceinline__ uint32_t smem_u32(const void* p) {
    uint32_t a;
    asm("{ .reg .u64 t; cvta.to.shared.u64 t, %1; cvt.u32.u64 %0, t; }" : "=r"(a) : "l"(p));
    return a;
}
__device__ __forceinline__ void cpasync16(uint32_t dst, const void* src) {
    asm volatile("cp.async.cg.shared.global [%0], [%1], 16;" :: "r"(dst), "l"(src));
}
__device__ __forceinline__ void ldsm4(uint32_t* r, uint32_t a) {
    asm volatile("ldmatrix.sync.aligned.m8n8.x4.shared.b16 {%0,%1,%2,%3}, [%4];"
                 : "=r"(r[0]), "=r"(r[1]), "=r"(r[2]), "=r"(r[3]) : "r"(a));
}
__device__ __forceinline__ void ldsm2(uint32_t* r, uint32_t a) {
    asm volatile("ldmatrix.sync.aligned.m8n8.x2.shared.b16 {%0,%1}, [%2];"
                 : "=r"(r[0]), "=r"(r[1]) : "r"(a));
}
__device__ __forceinline__ void mma16816(float* c, const uint32_t* a, const uint32_t* b) {
    asm volatile("mma.sync.aligned.m16n8k16.row.col.f32.bf16.bf16.f32 "
                 "{%0,%1,%2,%3}, {%4,%5,%6,%7}, {%8,%9}, {%0,%1,%2,%3};"
                 : "+f"(c[0]), "+f"(c[1]), "+f"(c[2]), "+f"(c[3])
                 : "r"(a[0]), "r"(a[1]), "r"(a[2]), "r"(a[3]), "r"(b[0]), "r"(b[1]));
}

// ---------------- scratch ----------------
__device__ float g_h[RR*DD], g_q[RR*DD], g_k[RR*DD], g_vt[DD*RR], g_att[RR*DD], g_h2[RR*DD];
__device__ float g_S[(long)GG*RR*RR], g_B1[(long)RR*GG*RR], g_B2[(long)RR*GG*RR];
__device__ __nv_bfloat16 g_xh[RR*KFC1], g_xl[RR*KFC1];
__device__ __nv_bfloat16 g_wh[DD*KFC1], g_wl[DD*KFC1];
__device__ __nv_bfloat16 g_hh[RR*DD],  g_hl[RR*DD];
__device__ __nv_bfloat16 g_qh[RR*DD],  g_ql[RR*DD];
__device__ __nv_bfloat16 g_kh[RR*DD],  g_kl[RR*DD];
__device__ __nv_bfloat16 g_vth[DD*RR], g_vtl[DD*RR];
__device__ __nv_bfloat16 g_cch[RR*3*DD], g_ccl[RR*3*DD];
__device__ __nv_bfloat16 g_Ph[(long)GG*RR*RR], g_Pl[(long)GG*RR*RR];

// ---------------- position bias ----------------
__global__ __launch_bounds__(128)
void posbias_kernel(const float* __restrict__ pe,
                    const float* __restrict__ Wp1, const float* __restrict__ bp1,
                    const float* __restrict__ Wp2, const float* __restrict__ bp2,
                    float* __restrict__ o1, float* __restrict__ o2)
{
    const int r = blockIdx.x, n = blockIdx.y * 128 + threadIdx.x;
    __shared__ float w1[GG][EE], w2[GG][EE], b1s[GG], b2s[GG];
    for (int i = threadIdx.x; i < GG*EE; i += 128) { w1[i>>6][i&63] = Wp1[i]; w2[i>>6][i&63] = Wp2[i]; }
    if (threadIdx.x < GG) { b1s[threadIdx.x] = bp1[threadIdx.x]; b2s[threadIdx.x] = bp2[threadIdx.x]; }
    __syncthreads();
    float4 pr[EE/4];
    const float4* src = (const float4*)(pe + (((long)r * RR) + n) * EE);
#pragma unroll
    for (int i = 0; i < EE/4; i++) pr[i] = src[i];
#pragma unroll 1
    for (int g = 0; g < GG; ++g) {
        const float4* a = (const float4*)w1[g];
        const float4* b = (const float4*)w2[g];
        float s1 = 0.f, s2 = 0.f;
#pragma unroll
        for (int i = 0; i < EE/4; i++) {
            float4 p = pr[i], xx = a[i], yy = b[i];
            s1 += p.x*xx.x + p.y*xx.y + p.z*xx.z + p.w*xx.w;
            s2 += p.x*yy.x + p.y*yy.y + p.z*yy.z + p.w*yy.w;
        }
        long o = ((long)r * GG + g) * RR + n;
        o1[o] = logf(fmaxf(s1 + b1s[g], 1e-6f));
        o2[o] = logf(fmaxf(s2 + b2s[g], 1e-6f));
    }
}

// ---------------- fp32 -> bf16 hi/lo split ----------------
__global__ __launch_bounds__(256)
void splitk(const float* __restrict__ in, __nv_bfloat16* __restrict__ hi,
            __nv_bfloat16* __restrict__ lo, long n4)
{
    for (long i = (long)blockIdx.x * 256 + threadIdx.x; i < n4; i += (long)gridDim.x * 256) {
        float4 v = ((const float4*)in)[i];
        __nv_bfloat16 a = __float2bfloat16(v.x), b = __float2bfloat16(v.y);
        __nv_bfloat16 c = __float2bfloat16(v.z), d = __float2bfloat16(v.w);
        ((__nv_bfloat162*)hi)[2*i]   = __halves2bfloat162(a, b);
        ((__nv_bfloat162*)hi)[2*i+1] = __halves2bfloat162(c, d);
        ((__nv_bfloat162*)lo)[2*i]   = __halves2bfloat162(
            __float2bfloat16(v.x - __bfloat162float(a)), __float2bfloat16(v.y - __bfloat162float(b)));
        ((__nv_bfloat162*)lo)[2*i+1] = __halves2bfloat162(
            __float2bfloat16(v.z - __bfloat162float(c)), __float2bfloat16(v.w - __bfloat162float(d)));
    }
}

// virtual concat [h | a | h+a] -> bf16 hi/lo
__global__ __launch_bounds__(256)
void catsplit(const float* __restrict__ h, const float* __restrict__ a,
              __nv_bfloat16* __restrict__ hi, __nv_bfloat16* __restrict__ lo)
{
    long i = (long)blockIdx.x * 256 + threadIdx.x;
    long e = i * 4;
    int r = (int)(e / (3*DD)), c = (int)(e % (3*DD));
    float4 v;
    if (c < DD) v = *(const float4*)(h + (long)r*DD + c);
    else if (c < 2*DD) v = *(const float4*)(a + (long)r*DD + c - DD);
    else {
        float4 x = *(const float4*)(h + (long)r*DD + c - 2*DD);
        float4 y = *(const float4*)(a + (long)r*DD + c - 2*DD);
        v = make_float4(x.x+y.x, x.y+y.y, x.z+y.z, x.w+y.w);
    }
    __nv_bfloat16 a0 = __float2bfloat16(v.x), b0 = __float2bfloat16(v.y);
    __nv_bfloat16 c0 = __float2bfloat16(v.z), d0 = __float2bfloat16(v.w);
    ((__nv_bfloat162*)hi)[2*i]   = __halves2bfloat162(a0, b0);
    ((__nv_bfloat162*)hi)[2*i+1] = __halves2bfloat162(c0, d0);
    ((__nv_bfloat162*)lo)[2*i]   = __halves2bfloat162(
        __float2bfloat16(v.x - __bfloat162float(a0)), __float2bfloat16(v.y - __bfloat162float(b0)));
    ((__nv_bfloat162*)lo)[2*i+1] = __halves2bfloat162(
        __float2bfloat16(v.z - __bfloat162float(c0)), __float2bfloat16(v.w - __bfloat162float(d0)));
}

// ---------------- softmax: fp32 in, bf16 hi/lo out ----------------
__global__ __launch_bounds__(256)
void softmax_kernel(const float* __restrict__ S, const float* __restrict__ bias,
                    __nv_bfloat16* __restrict__ Ph, __nv_bfloat16* __restrict__ Pl)
{
    const int i = blockIdx.x, g = blockIdx.y, tid = threadIdx.x;
    const long base = ((long)g * RR + i) * RR;
    const float* row  = S + base;
    const float* brow = bias + ((long)i * GG + g) * RR;
    float w[4], mx = -1e30f;
#pragma unroll
    for (int j = 0; j < 4; j++) { w[j] = row[tid + j*256] + brow[tid + j*256]; mx = fmaxf(mx, w[j]); }
    __shared__ float red[8];
#pragma unroll
    for (int o = 16; o > 0; o >>= 1) mx = fmaxf(mx, __shfl_xor_sync(~0u, mx, o));
    if ((tid & 31) == 0) red[tid >> 5] = mx;
    __syncthreads();
    float m2 = red[0];
#pragma unroll
    for (int k = 1; k < 8; k++) m2 = fmaxf(m2, red[k]);
    float sum = 0.f;
#pragma unroll
    for (int j = 0; j < 4; j++) { w[j] = __expf(w[j] - m2); sum += w[j]; }
#pragma unroll
    for (int o = 16; o > 0; o >>= 1) sum += __shfl_xor_sync(~0u, sum, o);
    __syncthreads();
    if ((tid & 31) == 0) red[tid >> 5] = sum;
    __syncthreads();
    float s2 = 0.f;
#pragma unroll
    for (int k = 0; k < 8; k++) s2 += red[k];
    float inv = 1.f / s2;
#pragma unroll
    for (int j = 0; j < 4; j++) {
        float p = w[j] * inv;
        __nv_bfloat16 ph = __float2bfloat16(p);
        long o = base + tid + j*256;
        Ph[o] = ph;
        Pl[o] = __float2bfloat16(p - __bfloat162float(ph));
    }
}

// ---------------- mma.sync split-precision GEMM ----------------
// C[128 x 64 tile] = alpha*(Ah Bh^T + Al Bh^T + Ah Bl^T) + bias, opt relu.
// A:[M,K] bf16 hi/lo row-major; B:[N,K] bf16 hi/lo row-major. z-batch element offsets.
// 256 thr = 8 warps (4m x 2n), warp tile 32x32, mma m16n8k16, cp.async double buffer.
#define ATB  16384              // 128 x 64 bf16
#define BTB  8192               // 64 x 64 bf16
#define MBUF (2*ATB + 2*BTB)    // 49152: [Ah|Al|Bh|Bl]
#define MSMEM (2*MBUF)          // 98304

__global__ void __launch_bounds__(256)
mmag(const __nv_bfloat16* __restrict__ Ah, const __nv_bfloat16* __restrict__ Al, int lda, long aZ,
     const __nv_bfloat16* __restrict__ Bh, const __nv_bfloat16* __restrict__ Bl, int ldb, long bZ,
     float* __restrict__ C, int ldc, long cZ,
     int K, float alpha, const float* __restrict__ bias, long biasZ, int relu)
{
    extern __shared__ __align__(1024) char smem[];
    const uint32_t sb = smem_u32(smem);
    const int tid = threadIdx.x, lane = tid & 31, wid = tid >> 5;
    const int warp_m = wid & 3, warp_n = wid >> 2;       // 4 x 2
    const int m0 = blockIdx.y * 128, n0 = blockIdx.x * 64;
    const long z = blockIdx.z;
    Ah += z * aZ; Al += z * aZ; Bh += z * bZ; Bl += z * bZ; C += z * cZ;
    const float* bp = bias ? bias + z * biasZ : nullptr;

    float acc[2][4][4];
#pragma unroll
    for (int i = 0; i < 2; i++)
#pragma unroll
        for (int j = 0; j < 4; j++)
#pragma unroll
            for (int q = 0; q < 4; q++) acc[i][j][q] = 0.f;

    const int nc = K >> 6;

    auto load_chunk = [&](int c, int buf) {
        const int kk = c << 6;
        const uint32_t base = sb + buf * MBUF;
#pragma unroll
        for (int it = 0; it < 4; it++) {
            int idx = tid + it * 256;
            int row = idx >> 3, g = idx & 7;
            uint32_t d = base + SWZ(row*128 + g*16);
            long off = (long)(m0 + row) * lda + kk + g*8;
            cpasync16(d,       Ah + off);
            cpasync16(d + ATB, Al + off);
        }
#pragma unroll
        for (int it = 0; it < 2; it++) {
            int idx = tid + it * 256;
            int row = idx >> 3, g = idx & 7;
            uint32_t d = base + 2*ATB + SWZ(row*128 + g*16);
            long off = (long)(n0 + row) * ldb + kk + g*8;
            cpasync16(d,       Bh + off);
            cpasync16(d + BTB, Bl + off);
        }
        asm volatile("cp.async.commit_group;");
    };

    load_chunk(0, 0);

    const int rA  = warp_m*32 + (lane & 7) + ((lane >> 3) & 1)*8;   // + i*16
    const int cAb = ((lane >> 4) & 1) * 16;                          // + ks*32
    const int rB  = warp_n*32 + (lane & 7);                          // + j*8
    const int cBb = ((lane >> 3) & 1) * 16;                          // + ks*32

    for (int c = 0; c < nc; c++) {
        const int buf = c & 1;
        if (c + 1 < nc) load_chunk(c + 1, buf ^ 1);
        if (c + 1 < nc) asm volatile("cp.async.wait_group 1;");
        else            asm volatile("cp.async.wait_group 0;");
        __syncthreads();

        const uint32_t ab  = sb + buf * MBUF;
        const uint32_t alb = ab + ATB, bhb = ab + 2*ATB, blb = ab + 2*ATB + BTB;
#pragma unroll
        for (int ks = 0; ks < 4; ks++) {
            uint32_t ah[2][4], al[2][4], bh[4][2], bl[4][2];
#pragma unroll
            for (int i = 0; i < 2; i++) {
                uint32_t o = SWZ((rA + i*16)*128 + ks*32 + cAb);
                ldsm4(ah[i], ab + o);
                ldsm4(al[i], alb + o);
            }
#pragma unroll
            for (int j = 0; j < 4; j++) {
                uint32_t o = SWZ((rB + j*8)*128 + ks*32 + cBb);
                ldsm2(bh[j], bhb + o);
                ldsm2(bl[j], blb + o);
            }
#pragma unroll
            for (int i = 0; i < 2; i++)
#pragma unroll
                for (int j = 0; j < 4; j++) {
                    mma16816(acc[i][j], ah[i], bh[j]);
                    mma16816(acc[i][j], al[i], bh[j]);
                    mma16816(acc[i][j], ah[i], bl[j]);
                }
        }
        __syncthreads();
    }

    // epilogue
#pragma unroll
    for (int i = 0; i < 2; i++) {
        int m = m0 + warp_m*32 + i*16 + (lane >> 2);
#pragma unroll
        for (int j = 0; j < 4; j++) {
            int n = n0 + warp_n*32 + j*8 + (lane & 3)*2;
            float b0v = bp ? bp[n] : 0.f, b1v = bp ? bp[n+1] : 0.f;
            float r0 = acc[i][j][0]*alpha + b0v, r1 = acc[i][j][1]*alpha + b1v;
            float r2 = acc[i][j][2]*alpha + b0v, r3 = acc[i][j][3]*alpha + b1v;
            if (relu) { r0=fmaxf(r0,0.f); r1=fmaxf(r1,0.f); r2=fmaxf(r2,0.f); r3=fmaxf(r3,0.f); }
            *(float2*)(C + (long)m*ldc + n)       = make_float2(r0, r1);
            *(float2*)(C + (long)(m+8)*ldc + n)   = make_float2(r2, r3);
        }
    }
}

// ---------------- host orchestration ----------------
static __nv_bfloat16 *xh,*xl,*wh,*wl,*hh,*hl,*qh,*ql,*kh,*kl,*vth,*vtl,*cch,*ccl,*Ph,*Pl;
static float *h,*q,*k,*vt,*att,*h2,*S,*B1,*B2;

static inline void do_split(const float* s, __nv_bfloat16* hi, __nv_bfloat16* lo, long n) {
    long n4 = n >> 2;
    int grid = (int)((n4 + 255) / 256); if (grid > 4096) grid = 4096;
    splitk<<<grid, 256>>>(s, hi, lo, n4);
}

static void relation_block(const float* Wq, const float* bq, const float* Wk, const float* bk,
                           const float* Wo, const float* bo, const float* Wa, const float* ba,
                           const float* biasLog, float* outp)
{
    do_split(Wq, wh, wl, (long)DD*DD);
    mmag<<<dim3(16,8,1),256,MSMEM>>>(hh,hl,DD,0, wh,wl,DD,0, q,DD,0, DD,1.f, bq,0,0);
    do_split(Wk, wh, wl, (long)DD*DD);
    mmag<<<dim3(16,8,1),256,MSMEM>>>(hh,hl,DD,0, wh,wl,DD,0, k,DD,0, DD,1.f, bk,0,0);
    do_split(Wo, wh, wl, (long)DD*DD);
    mmag<<<dim3(16,8,1),256,MSMEM>>>(wh,wl,DD,0, hh,hl,DD,0, vt,RR,0, DD,1.f, nullptr,0,0);
    do_split(q,  qh,  ql,  (long)RR*DD);
    do_split(k,  kh,  kl,  (long)RR*DD);
    do_split(vt, vth, vtl, (long)DD*RR);
    // S[g] = 0.125 * Q_g K_g^T
    mmag<<<dim3(16,8,GG),256,MSMEM>>>(qh,ql,DD,DGB, kh,kl,DD,DGB,
                                      S,RR,(long)RR*RR, DGB,0.125f, nullptr,0,0);
    softmax_kernel<<<dim3(RR,GG),256>>>(S, biasLog, Ph, Pl);
    // att[:, g*64:] = P_g @ Vt_g^T + bo_g
    mmag<<<dim3(1,8,GG),256,MSMEM>>>(Ph,Pl,RR,(long)RR*RR, vth,vtl,RR,(long)DGB*RR,
                                     att,DD,DGB, RR,1.f, bo,DGB,0);
    catsplit<<<(RR*3*DD/4)/256, 256>>>(h, att, cch, ccl);
    do_split(Wa, wh, wl, (long)DD*3*DD);
    mmag<<<dim3(16,8,1),256,MSMEM>>>(cch,ccl,3*DD,0, wh,wl,3*DD,0,
                                     outp,DD,0, 3*DD,1.f, ba,0,1);
}

extern "C" void kernel_launch(void* const* d_in, const int* in_sizes, int n_in,
                              void* d_out, int out_size)
{
    const float* x    = (const float*)d_in[0];
    const float* pe   = (const float*)d_in[1];
    const float* Wfc1 = (const float*)d_in[2];  const float* bfc1 = (const float*)d_in[3];
    const float* Wfc2 = (const float*)d_in[4];  const float* bfc2 = (const float*)d_in[5];
    const float* Wp1  = (const float*)d_in[6];  const float* bp1  = (const float*)d_in[7];
    const float* Wq1  = (const float*)d_in[8];  const float* bq1  = (const float*)d_in[9];
    const float* Wk1  = (const float*)d_in[10]; const float* bk1  = (const float*)d_in[11];
    const float* Wo1  = (const float*)d_in[12]; const float* bo1  = (const float*)d_in[13];
    const float* Wa1  = (const float*)d_in[14]; const float* ba1  = (const float*)d_in[15];
    const float* Wp2  = (const float*)d_in[16]; const float* bp2  = (const float*)d_in[17];
    const float* Wq2  = (const float*)d_in[18]; const float* bq2  = (const float*)d_in[19];
    const float* Wk2  = (const float*)d_in[20]; const float* bk2  = (const float*)d_in[21];
    const float* Wo2  = (const float*)d_in[22]; const float* bo2  = (const float*)d_in[23];
    const float* Wa2  = (const float*)d_in[24]; const float* ba2  = (const float*)d_in[25];
    float* out = (float*)d_out;

    cudaFuncSetAttribute(mmag, cudaFuncAttributeMaxDynamicSharedMemorySize, MSMEM);

    cudaGetSymbolAddress((void**)&h, g_h);     cudaGetSymbolAddress((void**)&q, g_q);
    cudaGetSymbolAddress((void**)&k, g_k);     cudaGetSymbolAddress((void**)&vt, g_vt);
    cudaGetSymbolAddress((void**)&att, g_att); cudaGetSymbolAddress((void**)&h2, g_h2);
    cudaGetSymbolAddress((void**)&S, g_S);
    cudaGetSymbolAddress((void**)&B1, g_B1);   cudaGetSymbolAddress((void**)&B2, g_B2);
    cudaGetSymbolAddress((void**)&xh, g_xh);   cudaGetSymbolAddress((void**)&xl, g_xl);
    cudaGetSymbolAddress((void**)&wh, g_wh);   cudaGetSymbolAddress((void**)&wl, g_wl);
    cudaGetSymbolAddress((void**)&hh, g_hh);   cudaGetSymbolAddress((void**)&hl, g_hl);
    cudaGetSymbolAddress((void**)&qh, g_qh);   cudaGetSymbolAddress((void**)&ql, g_ql);
    cudaGetSymbolAddress((void**)&kh, g_kh);   cudaGetSymbolAddress((void**)&kl, g_kl);
    cudaGetSymbolAddress((void**)&vth, g_vth); cudaGetSymbolAddress((void**)&vtl, g_vtl);
    cudaGetSymbolAddress((void**)&cch, g_cch); cudaGetSymbolAddress((void**)&ccl, g_ccl);
    cudaGetSymbolAddress((void**)&Ph, g_Ph);   cudaGetSymbolAddress((void**)&Pl, g_Pl);

    posbias_kernel<<<dim3(RR, RR/128), 128>>>(pe, Wp1, bp1, Wp2, bp2, B1, B2);

    // fc1
    do_split(x, xh, xl, (long)RR*KFC1);
    do_split(Wfc1, wh, wl, (long)DD*KFC1);
    mmag<<<dim3(16,8,1),256,MSMEM>>>(xh,xl,KFC1,0, wh,wl,KFC1,0, h,DD,0, KFC1,1.f, bfc1,0,0);
    do_split(h, hh, hl, (long)RR*DD);

    // relation block 1 -> h2
    relation_block(Wq1,bq1, Wk1,bk1, Wo1,bo1, Wa1,ba1, B1, h2);

    // fc2
    do_split(h2, hh, hl, (long)RR*DD);
    do_split(Wfc2, wh, wl, (long)DD*DD);
    mmag<<<dim3(16,8,1),256,MSMEM>>>(hh,hl,DD,0, wh,wl,DD,0, h,DD,0, DD,1.f, bfc2,0,0);
    do_split(h, hh, hl, (long)RR*DD);

    // relation block 2 -> out
    relation_block(Wq2,bq2, Wk2,bk2, Wo2,bo2, Wa2,ba2, B2, out);
}